// round 14
// baseline (speedup 1.0000x reference)
#include <cuda_runtime.h>
#include <cuda_fp16.h>

#define N_NODES 50000
#define FEAT 128
#define EMB 64
#define NEDGE 1600000
#define NB 8192
#define CAP 128   // max in-degree bucket (Poisson(32): P(>128) ~ 0)
#define ZOFF (N_NODES << 7)   // byte offset of permanent zero row

// ---- scratch (device globals; zero-initialized at load) ----
__device__ __align__(16) float   g_acc[N_NODES * EMB];        // running even-power combo
__device__ __align__(16) float   g_hfin[NB * EMB];            // final spectral rows per list entry
__device__ __align__(16) __half2 g_f16a[(N_NODES + 1) * 32];  // gather copy (+zero row)
__device__ __align__(16) __half2 g_f16b[(N_NODES + 1) * 32];
__device__ float g_dinv[N_NODES];
__device__ int   g_cursor[N_NODES];          // per-dst fill cursor (reset in k_dinv)
__device__ int   g_cnt[N_NODES];             // frozen counts for spmv
__device__ int   g_colidx[N_NODES * CAP];    // padded buckets; entries are src*128 (byte offsets)
__device__ __align__(16) float g_Wcomb[EMB * EMB];   // W3 @ weight
__device__ float g_bcomb[EMB];                       // b3 @ weight

#define H2(x) (*(__half2*)&(x))

// ---- packed f32x2 helpers ----
typedef unsigned long long u64;
__device__ __forceinline__ u64 ffma2(u64 a, u64 b, u64 c) {
    u64 d;
    asm("fma.rn.f32x2 %0, %1, %2, %3;" : "=l"(d) : "l"(a), "l"(b), "l"(c));
    return d;
}
__device__ __forceinline__ u64 pack2(float x, float y) {
    u64 d; asm("mov.b64 %0, {%1, %2};" : "=l"(d) : "f"(x), "f"(y)); return d;
}
__device__ __forceinline__ u64 packss(float s) {
    u64 d; asm("mov.b64 %0, {%1, %1};" : "=l"(d) : "f"(s)); return d;
}
__device__ __forceinline__ float2 unpk(u64 v) {
    float2 r; asm("mov.b64 {%0, %1}, %2;" : "=f"(r.x), "=f"(r.y) : "l"(v)); return r;
}

// ---------------- scatter: 1 edge/thread for max atomic-latency hiding ----------------
__global__ void k_scatter(const int* __restrict__ src, const int* __restrict__ dst) {
    int e = blockIdx.x * blockDim.x + threadIdx.x;
    if (e < NEDGE) {
        int d = dst[e];
        int s = src[e];
        int p = atomicAdd(&g_cursor[d], 1);
        if (p < CAP) g_colidx[d * CAP + p] = s << 7;
    }
}

// ---------------- dinv: freeze counts + dinv + reset cursor (critical path) ----------------
__global__ void k_dinv() {
    int i = blockIdx.x * blockDim.x + threadIdx.x;
    if (i < N_NODES) {
        int c = g_cursor[i];
        g_cnt[i] = min(c, CAP);
        g_dinv[i] = rsqrtf(fmaxf((float)c, 1.0f));
        g_cursor[i] = 0;    // ready for next replay
    }
}

// ---------------- wcomb: Wcomb = W3 @ weight, bcomb = b3 @ weight (side stream) ----------------
__global__ void k_wcomb(const float* __restrict__ W3, const float* __restrict__ b3,
                        const float* __restrict__ weight) {
    int idx = blockIdx.x * blockDim.x + threadIdx.x;
    if (idx < EMB * EMB) {
        int k = idx / EMB, j = idx % EMB;
        float acc = 0.0f;
#pragma unroll 16
        for (int m = 0; m < FEAT; m++)
            acc = fmaf(W3[k * FEAT + m], weight[m * EMB + j], acc);
        g_Wcomb[idx] = acc;
    } else if (idx < EMB * EMB + EMB) {
        int j = idx - EMB * EMB;
        float acc = 0.0f;
#pragma unroll 16
        for (int m = 0; m < FEAT; m++)
            acc = fmaf(b3[m], weight[m * EMB + j], acc);
        g_bcomb[j] = acc;
    }
}

// ---------------- MLP: h = relu(relu(feat@W1+b1)@W2+b2) ----------------
// dinv-FREE (runs concurrently with scatter/prep):
// writes acc = 0.84375*h (fp32) and f16a = half(h) UNSCALED.
__global__ __launch_bounds__(256) void k_mlp(const float* __restrict__ feat,
                      const float* __restrict__ W1, const float* __restrict__ b1,
                      const float* __restrict__ W2, const float* __restrict__ b2) {
    __shared__ float sfT[FEAT][64];   // [k][node]
    __shared__ float sh1T[EMB][68];   // [k][node], padded stride
    int tid = threadIdx.x;
    int tx = tid & 15;
    int ty = tid >> 4;
    int nbase = blockIdx.x * 64;

    {   // load features transposed
        int n = tid & 63;
        int gn = nbase + n;
        bool ok = gn < N_NODES;
        for (int p = tid >> 6; p < 32; p += 4) {
            float4 v = ok ? ((const float4*)feat)[gn * 32 + p]
                          : make_float4(0.f, 0.f, 0.f, 0.f);
            sfT[4 * p + 0][n] = v.x; sfT[4 * p + 1][n] = v.y;
            sfT[4 * p + 2][n] = v.z; sfT[4 * p + 3][n] = v.w;
        }
    }
    __syncthreads();

    u64 A[4][2];
    {
        float4 bb = ((const float4*)b1)[tx];
        u64 i01 = pack2(bb.x, bb.y), i23 = pack2(bb.z, bb.w);
        for (int j = 0; j < 4; j++) { A[j][0] = i01; A[j][1] = i23; }
    }
    const ulonglong2* W1v = (const ulonglong2*)W1;
#pragma unroll 4
    for (int k = 0; k < FEAT; k++) {
        ulonglong2 w = W1v[k * 16 + tx];
        float4 sv = *(const float4*)&sfT[k][4 * ty];
        u64 s;
        s = packss(sv.x); A[0][0] = ffma2(s, w.x, A[0][0]); A[0][1] = ffma2(s, w.y, A[0][1]);
        s = packss(sv.y); A[1][0] = ffma2(s, w.x, A[1][0]); A[1][1] = ffma2(s, w.y, A[1][1]);
        s = packss(sv.z); A[2][0] = ffma2(s, w.x, A[2][0]); A[2][1] = ffma2(s, w.y, A[2][1]);
        s = packss(sv.w); A[3][0] = ffma2(s, w.x, A[3][0]); A[3][1] = ffma2(s, w.y, A[3][1]);
    }
    for (int j = 0; j < 4; j++) {
        float2 p0 = unpk(A[j][0]), p1 = unpk(A[j][1]);
        int n = 4 * ty + j;
        sh1T[4 * tx + 0][n] = fmaxf(p0.x, 0.f);
        sh1T[4 * tx + 1][n] = fmaxf(p0.y, 0.f);
        sh1T[4 * tx + 2][n] = fmaxf(p1.x, 0.f);
        sh1T[4 * tx + 3][n] = fmaxf(p1.y, 0.f);
    }
    __syncthreads();

    {
        float4 bb = ((const float4*)b2)[tx];
        u64 i01 = pack2(bb.x, bb.y), i23 = pack2(bb.z, bb.w);
        for (int j = 0; j < 4; j++) { A[j][0] = i01; A[j][1] = i23; }
    }
    const ulonglong2* W2v = (const ulonglong2*)W2;
#pragma unroll 4
    for (int k = 0; k < EMB; k++) {
        ulonglong2 w = W2v[k * 16 + tx];
        float4 sv = *(const float4*)&sh1T[k][4 * ty];
        u64 s;
        s = packss(sv.x); A[0][0] = ffma2(s, w.x, A[0][0]); A[0][1] = ffma2(s, w.y, A[0][1]);
        s = packss(sv.y); A[1][0] = ffma2(s, w.x, A[1][0]); A[1][1] = ffma2(s, w.y, A[1][1]);
        s = packss(sv.z); A[2][0] = ffma2(s, w.x, A[2][0]); A[2][1] = ffma2(s, w.y, A[2][1]);
        s = packss(sv.w); A[3][0] = ffma2(s, w.x, A[3][0]); A[3][1] = ffma2(s, w.y, A[3][1]);
    }
    for (int j = 0; j < 4; j++) {
        int node = nbase + 4 * ty + j;
        if (node < N_NODES) {
            float2 p0 = unpk(A[j][0]), p1 = unpk(A[j][1]);
            float h0 = fmaxf(p0.x, 0.f), h1 = fmaxf(p0.y, 0.f);
            float h2 = fmaxf(p1.x, 0.f), h3 = fmaxf(p1.y, 0.f);
            ((float4*)g_acc)[node * 16 + tx] =
                make_float4(0.84375f * h0, 0.84375f * h1, 0.84375f * h2, 0.84375f * h3);
            g_f16a[node * 32 + 2 * tx + 0] = __floats2half2_rn(h0, h1);
            g_f16a[node * 32 + 2 * tx + 1] = __floats2half2_rn(h2, h3);
        }
    }
}

// ---------------- scores: center_scores = feat[nodes] @ Wclf + bclf (side stream) ----------------
__global__ void k_scores(const float* __restrict__ feat,
                         const float* __restrict__ Wclf,
                         const float* __restrict__ bclf,
                         const int* __restrict__ nodes,
                         float* __restrict__ outs) {
    int gt = blockIdx.x * blockDim.x + threadIdx.x;
    int w = gt >> 5, lane = gt & 31;
    if (w >= NB) return;
    int nd = nodes[w];
    float a0 = 0.0f, a1 = 0.0f;
    for (int k = lane; k < FEAT; k += 32) {
        float v = feat[nd * FEAT + k];
        a0 = fmaf(v, Wclf[2 * k], a0);
        a1 = fmaf(v, Wclf[2 * k + 1], a1);
    }
#pragma unroll
    for (int o = 16; o; o >>= 1) {
        a0 += __shfl_down_sync(0xffffffffu, a0, o);
        a1 += __shfl_down_sync(0xffffffffu, a1, o);
    }
    if (lane == 0) {
        outs[2 * w] = a0 + bclf[0];
        outs[2 * w + 1] = a1 + bclf[1];
    }
}

// ---------------- scale: f16a[node] *= dinv[node]  (after mlp || dinv join) ----------------
__global__ void k_scale() {
    int i = blockIdx.x * blockDim.x + threadIdx.x;   // over N_NODES*8 uint4
    if (i < N_NODES * 8) {
        float din = g_dinv[i >> 3];
        uint4 v = ((uint4*)g_f16a)[i];
        float2 f0 = __half22float2(H2(v.x));
        float2 f1 = __half22float2(H2(v.y));
        float2 f2 = __half22float2(H2(v.z));
        float2 f3 = __half22float2(H2(v.w));
        __half2 h0 = __floats2half2_rn(f0.x * din, f0.y * din);
        __half2 h1 = __floats2half2_rn(f1.x * din, f1.y * din);
        __half2 h2 = __floats2half2_rn(f2.x * din, f2.y * din);
        __half2 h3 = __floats2half2_rn(f3.x * din, f3.y * din);
        uint4 o;
        o.x = *(unsigned*)&h0; o.y = *(unsigned*)&h1;
        o.z = *(unsigned*)&h2; o.w = *(unsigned*)&h3;
        ((uint4*)g_f16a)[i] = o;
    }
}

// ---------------- SpMV core (FROZEN R9 body): one warp per node ----------------
// Lane L: edge-slot group g=L>>3 (4 edges per gather), 16B slice q=L&7.
// Pairwise hadd2 then f32 accumulate (8 independent chains); regs 32.
// Tail handled by ONE predicated 32-edge chunk (OOB -> zero row).
__device__ __forceinline__ void spmv_gather(const char* lptr, const int* col, int cnt,
                                            int g, float& a0, float& a1, float& a2,
                                            float& a3, float& a4, float& a5,
                                            float& a6, float& a7) {
    int i = 0;
    for (; i + 32 <= cnt; i += 32) {
#pragma unroll
        for (int j = 0; j < 8; j += 2) {
            int oA = col[i + 4 * j + g];
            int oB = col[i + 4 * j + 4 + g];
            uint4 va = *(const uint4*)(lptr + oA);
            uint4 vb = *(const uint4*)(lptr + oB);
            __half2 h0 = __hadd2(H2(va.x), H2(vb.x));
            __half2 h1 = __hadd2(H2(va.y), H2(vb.y));
            __half2 h2 = __hadd2(H2(va.z), H2(vb.z));
            __half2 h3 = __hadd2(H2(va.w), H2(vb.w));
            float2 f;
            f = __half22float2(h0); a0 += f.x; a1 += f.y;
            f = __half22float2(h1); a2 += f.x; a3 += f.y;
            f = __half22float2(h2); a4 += f.x; a5 += f.y;
            f = __half22float2(h3); a6 += f.x; a7 += f.y;
        }
    }
    if (i < cnt) {   // predicated full chunk for the tail
#pragma unroll
        for (int j = 0; j < 8; j += 2) {
            int eA = i + 4 * j + g;
            int eB = i + 4 * j + 4 + g;
            int oA = (eA < cnt) ? col[eA] : ZOFF;
            int oB = (eB < cnt) ? col[eB] : ZOFF;
            uint4 va = *(const uint4*)(lptr + oA);
            uint4 vb = *(const uint4*)(lptr + oB);
            __half2 h0 = __hadd2(H2(va.x), H2(vb.x));
            __half2 h1 = __hadd2(H2(va.y), H2(vb.y));
            __half2 h2 = __hadd2(H2(va.z), H2(vb.z));
            __half2 h3 = __hadd2(H2(va.w), H2(vb.w));
            float2 f;
            f = __half22float2(h0); a0 += f.x; a1 += f.y;
            f = __half22float2(h1); a2 += f.x; a3 += f.y;
            f = __half22float2(h2); a4 += f.x; a5 += f.y;
            f = __half22float2(h3); a6 += f.x; a7 += f.y;
        }
    }
}

#define SPMV_REDUCE() do { \
    a0 += __shfl_xor_sync(0xffffffffu, a0, 8);  a0 += __shfl_xor_sync(0xffffffffu, a0, 16); \
    a1 += __shfl_xor_sync(0xffffffffu, a1, 8);  a1 += __shfl_xor_sync(0xffffffffu, a1, 16); \
    a2 += __shfl_xor_sync(0xffffffffu, a2, 8);  a2 += __shfl_xor_sync(0xffffffffu, a2, 16); \
    a3 += __shfl_xor_sync(0xffffffffu, a3, 8);  a3 += __shfl_xor_sync(0xffffffffu, a3, 16); \
    a4 += __shfl_xor_sync(0xffffffffu, a4, 8);  a4 += __shfl_xor_sync(0xffffffffu, a4, 16); \
    a5 += __shfl_xor_sync(0xffffffffu, a5, 8);  a5 += __shfl_xor_sync(0xffffffffu, a5, 16); \
    a6 += __shfl_xor_sync(0xffffffffu, a6, 8);  a6 += __shfl_xor_sync(0xffffffffu, a6, 16); \
    a7 += __shfl_xor_sync(0xffffffffu, a7, 8);  a7 += __shfl_xor_sync(0xffffffffu, a7, 16); \
} while (0)

template <bool DO_ACC, bool DO_OUT>
__global__ __launch_bounds__(256, 7) void k_spmv(int parity, float coefAcc) {
    const char* __restrict__ inb = (const char*)(parity ? g_f16b : g_f16a);
    uint4* __restrict__ out = (uint4*)(parity ? g_f16a : g_f16b);
    int lane = threadIdx.x & 31;
    int d = blockIdx.x * 8 + (threadIdx.x >> 5);  // grid = 6250 exact
    int cnt = g_cnt[d];
    const int* __restrict__ col = g_colidx + d * CAP;
    int g = lane >> 3;
    int q = lane & 7;
    const char* lptr = inb + q * 16;

    float a0 = 0.f, a1 = 0.f, a2 = 0.f, a3 = 0.f;
    float a4 = 0.f, a5 = 0.f, a6 = 0.f, a7 = 0.f;
    spmv_gather(lptr, col, cnt, g, a0, a1, a2, a3, a4, a5, a6, a7);
    SPMV_REDUCE();

    float din = g_dinv[d];
    if (DO_OUT && lane < 8) {
        float s2 = din * din;   // out = (a*din)*din for next pre-scaled gather
        __half2 h0 = __floats2half2_rn(a0 * s2, a1 * s2);
        __half2 h1 = __floats2half2_rn(a2 * s2, a3 * s2);
        __half2 h2 = __floats2half2_rn(a4 * s2, a5 * s2);
        __half2 h3 = __floats2half2_rn(a6 * s2, a7 * s2);
        uint4 o;
        o.x = *(unsigned*)&h0; o.y = *(unsigned*)&h1;
        o.z = *(unsigned*)&h2; o.w = *(unsigned*)&h3;
        out[d * 8 + q] = o;
    }
    if (DO_ACC && lane >= 8 && lane < 16) {
        float c = coefAcc * din;    // acc += coef * (a*din)
        float4* ap = (float4*)&g_acc[d * 64 + q * 8];
        float4 x = ap[0], y = ap[1];
        x.x = fmaf(c, a0, x.x); x.y = fmaf(c, a1, x.y);
        x.z = fmaf(c, a2, x.z); x.w = fmaf(c, a3, x.w);
        y.x = fmaf(c, a4, y.x); y.y = fmaf(c, a5, y.y);
        y.z = fmaf(c, a6, y.z); y.w = fmaf(c, a7, y.w);
        ap[0] = x; ap[1] = y;
    }
}

// ---------------- stage 6 at list entries only ----------------
__global__ __launch_bounds__(256, 7) void k_spmv6(const int* __restrict__ nodes,
                                                  float coefAcc) {
    const char* __restrict__ inb = (const char*)g_f16b;   // a5 lives in buffer b
    int lane = threadIdx.x & 31;
    int wi = blockIdx.x * 8 + (threadIdx.x >> 5);  // grid = NB/8 = 1024 exact
    int d = nodes[wi];
    int cnt = g_cnt[d];
    const int* __restrict__ col = g_colidx + d * CAP;
    int g = lane >> 3;
    int q = lane & 7;
    const char* lptr = inb + q * 16;

    float a0 = 0.f, a1 = 0.f, a2 = 0.f, a3 = 0.f;
    float a4 = 0.f, a5 = 0.f, a6 = 0.f, a7 = 0.f;
    spmv_gather(lptr, col, cnt, g, a0, a1, a2, a3, a4, a5, a6, a7);
    SPMV_REDUCE();

    if (lane < 8) {
        float c = coefAcc * g_dinv[d];
        const float4* ap = (const float4*)&g_acc[d * 64 + q * 8];
        float4 x = ap[0], y = ap[1];
        x.x = fmaf(c, a0, x.x); x.y = fmaf(c, a1, x.y);
        x.z = fmaf(c, a2, x.z); x.w = fmaf(c, a3, x.w);
        y.x = fmaf(c, a4, y.x); y.y = fmaf(c, a5, y.y);
        y.z = fmaf(c, a6, y.z); y.w = fmaf(c, a7, y.w);
        float4* hp = (float4*)&g_hfin[wi * 64 + q * 8];
        hp[0] = x; hp[1] = y;
    }
}

// ---------------- final: combined only (scores on side stream) ----------------
#define FIN_BLKS (NB / 16)    // 512
__global__ void k_final(const float* __restrict__ feat,
                        const float* __restrict__ weight,
                        const int* __restrict__ nodes,
                        float* __restrict__ outc) {
    int tx = threadIdx.x;
    int ty = threadIdx.y;
    int tid = ty * 16 + tx;

    __shared__ float sf[16][FEAT];
    __shared__ float shh[16][EMB];
    __shared__ int snd[16];
    int ibase = blockIdx.x * 16;

    if (tid < 16) snd[tid] = nodes[ibase + tid];
    __syncthreads();

    const float4* f4 = (const float4*)feat;
    const float4* h4 = (const float4*)g_hfin;   // coalesced per-entry rows
    for (int e = tid; e < 16 * 32; e += 256) {
        int n = e >> 5, k4 = e & 31;
        ((float4*)sf[n])[k4] = f4[snd[n] * 32 + k4];
    }
    for (int e = tid; e < 16 * 16; e += 256) {
        int n = e >> 4, k4 = e & 15;
        ((float4*)shh[n])[k4] = h4[ibase * 16 + e];
    }
    __syncthreads();

    float4 b = ((const float4*)g_bcomb)[tx];
    u64 A01 = pack2(b.x, b.y), A23 = pack2(b.z, b.w);
    const ulonglong2* Wv = (const ulonglong2*)weight;
#pragma unroll 8
    for (int k = 0; k < FEAT; k++) {
        u64 s = packss(sf[ty][k]);
        ulonglong2 w = Wv[k * 16 + tx];
        A01 = ffma2(s, w.x, A01);
        A23 = ffma2(s, w.y, A23);
    }
    const ulonglong2* Wc = (const ulonglong2*)g_Wcomb;
#pragma unroll 8
    for (int k = 0; k < EMB; k++) {
        u64 s = packss(shh[ty][k]);
        ulonglong2 w = Wc[k * 16 + tx];
        A01 = ffma2(s, w.x, A01);
        A23 = ffma2(s, w.y, A23);
    }
    float2 p0 = unpk(A01), p1 = unpk(A23);
    float4 o;
    o.x = fmaxf(p0.x, 0.0f); o.y = fmaxf(p0.y, 0.0f);
    o.z = fmaxf(p1.x, 0.0f); o.w = fmaxf(p1.y, 0.0f);
    ((float4*)outc)[(ibase + ty) * 16 + tx] = o;
}

extern "C" void kernel_launch(void* const* d_in, const int* in_sizes, int n_in,
                              void* d_out, int out_size) {
    const float* feat = (const float*)d_in[0];
    const float* Wclf = (const float*)d_in[1];
    const float* bclf = (const float*)d_in[2];
    const float* W1 = (const float*)d_in[3];
    const float* b1 = (const float*)d_in[4];
    const float* W2 = (const float*)d_in[5];
    const float* b2 = (const float*)d_in[6];
    const float* W3 = (const float*)d_in[7];
    const float* b3 = (const float*)d_in[8];
    const float* weight = (const float*)d_in[9];
    const int* nodes = (const int*)d_in[10];
    // d_in[11] = r1_neighs: dead branch (AGG_WEIGHT[0] == 0.0)
    const int* esrc = (const int*)d_in[12];
    const int* edst = (const int*)d_in[13];

    float* outc = (float*)d_out;          // [8192, 64]
    float* outs = outc + NB * EMB;        // [8192, 2]

    // Side stream: (dinv-free) MLP + wcomb + scores, overlapped with scatter/chain.
    cudaStream_t s2;
    cudaStreamCreateWithFlags(&s2, cudaStreamNonBlocking);
    cudaEvent_t evFork, evJoin, evJoin2;
    cudaEventCreateWithFlags(&evFork, cudaEventDisableTiming);
    cudaEventCreateWithFlags(&evJoin, cudaEventDisableTiming);
    cudaEventCreateWithFlags(&evJoin2, cudaEventDisableTiming);

    cudaEventRecord(evFork, 0);
    cudaStreamWaitEvent(s2, evFork, 0);
    k_mlp<<<(N_NODES + 63) / 64, 256, 0, s2>>>(feat, W1, b1, W2, b2);
    cudaEventRecord(evJoin, s2);          // mlp done (k_scale dependency)
    k_wcomb<<<17, 256, 0, s2>>>(W3, b3, weight);
    k_scores<<<NB * 32 / 256, 256, 0, s2>>>(feat, Wclf, bclf, nodes, outs);
    cudaEventRecord(evJoin2, s2);         // wcomb+scores done (k_final dependency)

    // Main (capture) stream: g_cursor is zero here (zero-init; reset in k_dinv).
    k_scatter<<<(NEDGE + 255) / 256, 256>>>(esrc, edst);
    k_dinv<<<(N_NODES + 255) / 256, 256>>>();

    cudaStreamWaitEvent(0, evJoin, 0);    // join mlp branch
    k_scale<<<(N_NODES * 8 + 255) / 256, 256>>>();   // f16a *= dinv

    // Factored chain: h_final = 0.84375 h - 2.53125 A^2 h + 2.53125 A^4 h - 0.84375 A^6 h
    // Stages 1-5 over all nodes; stage 6 only at the 8192 output list entries.
    const int SB = N_NODES / 8;
    k_spmv<false, true ><<<SB, 256>>>(0, 0.0f);        // a1 = A h     (a -> b)
    k_spmv<true,  true ><<<SB, 256>>>(1, -2.53125f);   // a2, acc -= 2.53125 a2
    k_spmv<false, true ><<<SB, 256>>>(0, 0.0f);        // a3
    k_spmv<true,  true ><<<SB, 256>>>(1, 2.53125f);    // a4, acc += 2.53125 a4
    k_spmv<false, true ><<<SB, 256>>>(0, 0.0f);        // a5           (a -> b)
    k_spmv6<<<NB / 8, 256>>>(nodes, -0.84375f);        // hfin[i] = acc - 0.84375 (A a5)

    cudaStreamWaitEvent(0, evJoin2, 0);   // ensure wcomb+scores precede k_final
    dim3 b16x16(16, 16);
    k_final<<<FIN_BLKS, b16x16>>>(feat, weight, nodes, outc);

    cudaEventDestroy(evFork);
    cudaEventDestroy(evJoin);
    cudaEventDestroy(evJoin2);
    cudaStreamDestroy(s2);
    (void)in_sizes; (void)n_in; (void)out_size;
}

// round 15
// speedup vs baseline: 1.0062x; 1.0062x over previous
#include <cuda_runtime.h>
#include <cuda_fp16.h>

#define N_NODES 50000
#define FEAT 128
#define EMB 64
#define NEDGE 1600000
#define NB 8192
#define CAP 128   // max in-degree bucket (Poisson(32): P(>128) ~ 0)
#define ZOFF (N_NODES << 7)   // byte offset of permanent zero row

// ---- scratch (device globals; zero-initialized at load) ----
__device__ __align__(16) float   g_acc[N_NODES * EMB];        // running even-power combo
__device__ __align__(16) float   g_hfin[NB * EMB];            // final spectral rows per list entry
__device__ __align__(16) __half2 g_f16a[(N_NODES + 1) * 32];  // gather copy (+zero row)
__device__ __align__(16) __half2 g_f16b[(N_NODES + 1) * 32];
__device__ float g_dinv[N_NODES];
__device__ int   g_cursor[N_NODES];          // per-dst fill cursor (reset in k_dinv)
__device__ int   g_cnt[N_NODES];             // frozen counts for spmv
__device__ int   g_colidx[N_NODES * CAP];    // padded buckets; entries are src*128 (byte offsets)
__device__ __align__(16) float g_Wcomb[EMB * EMB];   // W3 @ weight
__device__ float g_bcomb[EMB];                       // b3 @ weight

#define H2(x) (*(__half2*)&(x))

// ---- packed f32x2 helpers ----
typedef unsigned long long u64;
__device__ __forceinline__ u64 ffma2(u64 a, u64 b, u64 c) {
    u64 d;
    asm("fma.rn.f32x2 %0, %1, %2, %3;" : "=l"(d) : "l"(a), "l"(b), "l"(c));
    return d;
}
__device__ __forceinline__ u64 pack2(float x, float y) {
    u64 d; asm("mov.b64 %0, {%1, %2};" : "=l"(d) : "f"(x), "f"(y)); return d;
}
__device__ __forceinline__ u64 packss(float s) {
    u64 d; asm("mov.b64 %0, {%1, %1};" : "=l"(d) : "f"(s)); return d;
}
__device__ __forceinline__ float2 unpk(u64 v) {
    float2 r; asm("mov.b64 {%0, %1}, %2;" : "=f"(r.x), "=f"(r.y) : "l"(v)); return r;
}

// ---------------- scatter: 1 edge/thread for max atomic-latency hiding ----------------
__global__ void k_scatter(const int* __restrict__ src, const int* __restrict__ dst) {
    int e = blockIdx.x * blockDim.x + threadIdx.x;
    if (e < NEDGE) {
        int d = dst[e];
        int s = src[e];
        int p = atomicAdd(&g_cursor[d], 1);
        if (p < CAP) g_colidx[d * CAP + p] = s << 7;
    }
}

// ---------------- dinv: freeze counts + dinv + reset cursor (critical path) ----------------
__global__ void k_dinv() {
    int i = blockIdx.x * blockDim.x + threadIdx.x;
    if (i < N_NODES) {
        int c = g_cursor[i];
        g_cnt[i] = min(c, CAP);
        g_dinv[i] = rsqrtf(fmaxf((float)c, 1.0f));
        g_cursor[i] = 0;    // ready for next replay
    }
}

// ---------------- wcomb: Wcomb = W3 @ weight, bcomb = b3 @ weight (side stream) ----------------
__global__ void k_wcomb(const float* __restrict__ W3, const float* __restrict__ b3,
                        const float* __restrict__ weight) {
    int idx = blockIdx.x * blockDim.x + threadIdx.x;
    if (idx < EMB * EMB) {
        int k = idx / EMB, j = idx % EMB;
        float acc = 0.0f;
#pragma unroll 16
        for (int m = 0; m < FEAT; m++)
            acc = fmaf(W3[k * FEAT + m], weight[m * EMB + j], acc);
        g_Wcomb[idx] = acc;
    } else if (idx < EMB * EMB + EMB) {
        int j = idx - EMB * EMB;
        float acc = 0.0f;
#pragma unroll 16
        for (int m = 0; m < FEAT; m++)
            acc = fmaf(b3[m], weight[m * EMB + j], acc);
        g_bcomb[j] = acc;
    }
}

// ---------------- MLP: h = relu(relu(feat@W1+b1)@W2+b2) ----------------
// dinv-FREE (runs concurrently with scatter/prep):
// writes acc = 0.84375*h (fp32) and f16a = half(h) UNSCALED.
__global__ __launch_bounds__(256) void k_mlp(const float* __restrict__ feat,
                      const float* __restrict__ W1, const float* __restrict__ b1,
                      const float* __restrict__ W2, const float* __restrict__ b2) {
    __shared__ float sfT[FEAT][64];   // [k][node]
    __shared__ float sh1T[EMB][68];   // [k][node], padded stride
    int tid = threadIdx.x;
    int tx = tid & 15;
    int ty = tid >> 4;
    int nbase = blockIdx.x * 64;

    {   // load features transposed
        int n = tid & 63;
        int gn = nbase + n;
        bool ok = gn < N_NODES;
        for (int p = tid >> 6; p < 32; p += 4) {
            float4 v = ok ? ((const float4*)feat)[gn * 32 + p]
                          : make_float4(0.f, 0.f, 0.f, 0.f);
            sfT[4 * p + 0][n] = v.x; sfT[4 * p + 1][n] = v.y;
            sfT[4 * p + 2][n] = v.z; sfT[4 * p + 3][n] = v.w;
        }
    }
    __syncthreads();

    u64 A[4][2];
    {
        float4 bb = ((const float4*)b1)[tx];
        u64 i01 = pack2(bb.x, bb.y), i23 = pack2(bb.z, bb.w);
        for (int j = 0; j < 4; j++) { A[j][0] = i01; A[j][1] = i23; }
    }
    const ulonglong2* W1v = (const ulonglong2*)W1;
#pragma unroll 4
    for (int k = 0; k < FEAT; k++) {
        ulonglong2 w = W1v[k * 16 + tx];
        float4 sv = *(const float4*)&sfT[k][4 * ty];
        u64 s;
        s = packss(sv.x); A[0][0] = ffma2(s, w.x, A[0][0]); A[0][1] = ffma2(s, w.y, A[0][1]);
        s = packss(sv.y); A[1][0] = ffma2(s, w.x, A[1][0]); A[1][1] = ffma2(s, w.y, A[1][1]);
        s = packss(sv.z); A[2][0] = ffma2(s, w.x, A[2][0]); A[2][1] = ffma2(s, w.y, A[2][1]);
        s = packss(sv.w); A[3][0] = ffma2(s, w.x, A[3][0]); A[3][1] = ffma2(s, w.y, A[3][1]);
    }
    for (int j = 0; j < 4; j++) {
        float2 p0 = unpk(A[j][0]), p1 = unpk(A[j][1]);
        int n = 4 * ty + j;
        sh1T[4 * tx + 0][n] = fmaxf(p0.x, 0.f);
        sh1T[4 * tx + 1][n] = fmaxf(p0.y, 0.f);
        sh1T[4 * tx + 2][n] = fmaxf(p1.x, 0.f);
        sh1T[4 * tx + 3][n] = fmaxf(p1.y, 0.f);
    }
    __syncthreads();

    {
        float4 bb = ((const float4*)b2)[tx];
        u64 i01 = pack2(bb.x, bb.y), i23 = pack2(bb.z, bb.w);
        for (int j = 0; j < 4; j++) { A[j][0] = i01; A[j][1] = i23; }
    }
    const ulonglong2* W2v = (const ulonglong2*)W2;
#pragma unroll 4
    for (int k = 0; k < EMB; k++) {
        ulonglong2 w = W2v[k * 16 + tx];
        float4 sv = *(const float4*)&sh1T[k][4 * ty];
        u64 s;
        s = packss(sv.x); A[0][0] = ffma2(s, w.x, A[0][0]); A[0][1] = ffma2(s, w.y, A[0][1]);
        s = packss(sv.y); A[1][0] = ffma2(s, w.x, A[1][0]); A[1][1] = ffma2(s, w.y, A[1][1]);
        s = packss(sv.z); A[2][0] = ffma2(s, w.x, A[2][0]); A[2][1] = ffma2(s, w.y, A[2][1]);
        s = packss(sv.w); A[3][0] = ffma2(s, w.x, A[3][0]); A[3][1] = ffma2(s, w.y, A[3][1]);
    }
    for (int j = 0; j < 4; j++) {
        int node = nbase + 4 * ty + j;
        if (node < N_NODES) {
            float2 p0 = unpk(A[j][0]), p1 = unpk(A[j][1]);
            float h0 = fmaxf(p0.x, 0.f), h1 = fmaxf(p0.y, 0.f);
            float h2 = fmaxf(p1.x, 0.f), h3 = fmaxf(p1.y, 0.f);
            ((float4*)g_acc)[node * 16 + tx] =
                make_float4(0.84375f * h0, 0.84375f * h1, 0.84375f * h2, 0.84375f * h3);
            g_f16a[node * 32 + 2 * tx + 0] = __floats2half2_rn(h0, h1);
            g_f16a[node * 32 + 2 * tx + 1] = __floats2half2_rn(h2, h3);
        }
    }
}

// ---------------- scores: center_scores = feat[nodes] @ Wclf + bclf (side stream) ----------------
__global__ void k_scores(const float* __restrict__ feat,
                         const float* __restrict__ Wclf,
                         const float* __restrict__ bclf,
                         const int* __restrict__ nodes,
                         float* __restrict__ outs) {
    int gt = blockIdx.x * blockDim.x + threadIdx.x;
    int w = gt >> 5, lane = gt & 31;
    if (w >= NB) return;
    int nd = nodes[w];
    float a0 = 0.0f, a1 = 0.0f;
    for (int k = lane; k < FEAT; k += 32) {
        float v = feat[nd * FEAT + k];
        a0 = fmaf(v, Wclf[2 * k], a0);
        a1 = fmaf(v, Wclf[2 * k + 1], a1);
    }
#pragma unroll
    for (int o = 16; o; o >>= 1) {
        a0 += __shfl_down_sync(0xffffffffu, a0, o);
        a1 += __shfl_down_sync(0xffffffffu, a1, o);
    }
    if (lane == 0) {
        outs[2 * w] = a0 + bclf[0];
        outs[2 * w + 1] = a1 + bclf[1];
    }
}

// ---------------- scale: f16a[node] *= dinv[node]  (after mlp || dinv join) ----------------
__global__ void k_scale() {
    int i = blockIdx.x * blockDim.x + threadIdx.x;   // over N_NODES*8 uint4
    if (i < N_NODES * 8) {
        float din = g_dinv[i >> 3];
        uint4 v = ((uint4*)g_f16a)[i];
        float2 f0 = __half22float2(H2(v.x));
        float2 f1 = __half22float2(H2(v.y));
        float2 f2 = __half22float2(H2(v.z));
        float2 f3 = __half22float2(H2(v.w));
        __half2 h0 = __floats2half2_rn(f0.x * din, f0.y * din);
        __half2 h1 = __floats2half2_rn(f1.x * din, f1.y * din);
        __half2 h2 = __floats2half2_rn(f2.x * din, f2.y * din);
        __half2 h3 = __floats2half2_rn(f3.x * din, f3.y * din);
        uint4 o;
        o.x = *(unsigned*)&h0; o.y = *(unsigned*)&h1;
        o.z = *(unsigned*)&h2; o.w = *(unsigned*)&h3;
        ((uint4*)g_f16a)[i] = o;
    }
}

// ---------------- SpMV core (FROZEN R9 body): one warp per node ----------------
// Lane L: edge-slot group g=L>>3 (4 edges per gather), 16B slice q=L&7.
// Pairwise hadd2 then f32 accumulate (8 independent chains); regs 32.
// Tail handled by ONE predicated 32-edge chunk (OOB -> zero row).
__device__ __forceinline__ void spmv_gather(const char* lptr, const int* col, int cnt,
                                            int g, float& a0, float& a1, float& a2,
                                            float& a3, float& a4, float& a5,
                                            float& a6, float& a7) {
    int i = 0;
    for (; i + 32 <= cnt; i += 32) {
#pragma unroll
        for (int j = 0; j < 8; j += 2) {
            int oA = col[i + 4 * j + g];
            int oB = col[i + 4 * j + 4 + g];
            uint4 va = *(const uint4*)(lptr + oA);
            uint4 vb = *(const uint4*)(lptr + oB);
            __half2 h0 = __hadd2(H2(va.x), H2(vb.x));
            __half2 h1 = __hadd2(H2(va.y), H2(vb.y));
            __half2 h2 = __hadd2(H2(va.z), H2(vb.z));
            __half2 h3 = __hadd2(H2(va.w), H2(vb.w));
            float2 f;
            f = __half22float2(h0); a0 += f.x; a1 += f.y;
            f = __half22float2(h1); a2 += f.x; a3 += f.y;
            f = __half22float2(h2); a4 += f.x; a5 += f.y;
            f = __half22float2(h3); a6 += f.x; a7 += f.y;
        }
    }
    if (i < cnt) {   // predicated full chunk for the tail
#pragma unroll
        for (int j = 0; j < 8; j += 2) {
            int eA = i + 4 * j + g;
            int eB = i + 4 * j + 4 + g;
            int oA = (eA < cnt) ? col[eA] : ZOFF;
            int oB = (eB < cnt) ? col[eB] : ZOFF;
            uint4 va = *(const uint4*)(lptr + oA);
            uint4 vb = *(const uint4*)(lptr + oB);
            __half2 h0 = __hadd2(H2(va.x), H2(vb.x));
            __half2 h1 = __hadd2(H2(va.y), H2(vb.y));
            __half2 h2 = __hadd2(H2(va.z), H2(vb.z));
            __half2 h3 = __hadd2(H2(va.w), H2(vb.w));
            float2 f;
            f = __half22float2(h0); a0 += f.x; a1 += f.y;
            f = __half22float2(h1); a2 += f.x; a3 += f.y;
            f = __half22float2(h2); a4 += f.x; a5 += f.y;
            f = __half22float2(h3); a6 += f.x; a7 += f.y;
        }
    }
}

#define SPMV_REDUCE() do { \
    a0 += __shfl_xor_sync(0xffffffffu, a0, 8);  a0 += __shfl_xor_sync(0xffffffffu, a0, 16); \
    a1 += __shfl_xor_sync(0xffffffffu, a1, 8);  a1 += __shfl_xor_sync(0xffffffffu, a1, 16); \
    a2 += __shfl_xor_sync(0xffffffffu, a2, 8);  a2 += __shfl_xor_sync(0xffffffffu, a2, 16); \
    a3 += __shfl_xor_sync(0xffffffffu, a3, 8);  a3 += __shfl_xor_sync(0xffffffffu, a3, 16); \
    a4 += __shfl_xor_sync(0xffffffffu, a4, 8);  a4 += __shfl_xor_sync(0xffffffffu, a4, 16); \
    a5 += __shfl_xor_sync(0xffffffffu, a5, 8);  a5 += __shfl_xor_sync(0xffffffffu, a5, 16); \
    a6 += __shfl_xor_sync(0xffffffffu, a6, 8);  a6 += __shfl_xor_sync(0xffffffffu, a6, 16); \
    a7 += __shfl_xor_sync(0xffffffffu, a7, 8);  a7 += __shfl_xor_sync(0xffffffffu, a7, 16); \
} while (0)

template <bool DO_ACC, bool DO_OUT>
__global__ __launch_bounds__(256, 8) void k_spmv(int parity, float coefAcc) {
    const char* __restrict__ inb = (const char*)(parity ? g_f16b : g_f16a);
    uint4* __restrict__ out = (uint4*)(parity ? g_f16a : g_f16b);
    int lane = threadIdx.x & 31;
    int d = blockIdx.x * 8 + (threadIdx.x >> 5);  // grid = 6250 exact
    int cnt = g_cnt[d];
    const int* __restrict__ col = g_colidx + d * CAP;
    int g = lane >> 3;
    int q = lane & 7;
    const char* lptr = inb + q * 16;

    float a0 = 0.f, a1 = 0.f, a2 = 0.f, a3 = 0.f;
    float a4 = 0.f, a5 = 0.f, a6 = 0.f, a7 = 0.f;
    spmv_gather(lptr, col, cnt, g, a0, a1, a2, a3, a4, a5, a6, a7);
    SPMV_REDUCE();

    float din = g_dinv[d];
    if (DO_OUT && lane < 8) {
        float s2 = din * din;   // out = (a*din)*din for next pre-scaled gather
        __half2 h0 = __floats2half2_rn(a0 * s2, a1 * s2);
        __half2 h1 = __floats2half2_rn(a2 * s2, a3 * s2);
        __half2 h2 = __floats2half2_rn(a4 * s2, a5 * s2);
        __half2 h3 = __floats2half2_rn(a6 * s2, a7 * s2);
        uint4 o;
        o.x = *(unsigned*)&h0; o.y = *(unsigned*)&h1;
        o.z = *(unsigned*)&h2; o.w = *(unsigned*)&h3;
        out[d * 8 + q] = o;
    }
    if (DO_ACC && lane >= 8 && lane < 16) {
        float c = coefAcc * din;    // acc += coef * (a*din)
        float4* ap = (float4*)&g_acc[d * 64 + q * 8];
        float4 x = ap[0], y = ap[1];
        x.x = fmaf(c, a0, x.x); x.y = fmaf(c, a1, x.y);
        x.z = fmaf(c, a2, x.z); x.w = fmaf(c, a3, x.w);
        y.x = fmaf(c, a4, y.x); y.y = fmaf(c, a5, y.y);
        y.z = fmaf(c, a6, y.z); y.w = fmaf(c, a7, y.w);
        ap[0] = x; ap[1] = y;
    }
}

// ---------------- stage 6 at list entries only ----------------
__global__ __launch_bounds__(256, 8) void k_spmv6(const int* __restrict__ nodes,
                                                  float coefAcc) {
    const char* __restrict__ inb = (const char*)g_f16b;   // a5 lives in buffer b
    int lane = threadIdx.x & 31;
    int wi = blockIdx.x * 8 + (threadIdx.x >> 5);  // grid = NB/8 = 1024 exact
    int d = nodes[wi];
    int cnt = g_cnt[d];
    const int* __restrict__ col = g_colidx + d * CAP;
    int g = lane >> 3;
    int q = lane & 7;
    const char* lptr = inb + q * 16;

    float a0 = 0.f, a1 = 0.f, a2 = 0.f, a3 = 0.f;
    float a4 = 0.f, a5 = 0.f, a6 = 0.f, a7 = 0.f;
    spmv_gather(lptr, col, cnt, g, a0, a1, a2, a3, a4, a5, a6, a7);
    SPMV_REDUCE();

    if (lane < 8) {
        float c = coefAcc * g_dinv[d];
        const float4* ap = (const float4*)&g_acc[d * 64 + q * 8];
        float4 x = ap[0], y = ap[1];
        x.x = fmaf(c, a0, x.x); x.y = fmaf(c, a1, x.y);
        x.z = fmaf(c, a2, x.z); x.w = fmaf(c, a3, x.w);
        y.x = fmaf(c, a4, y.x); y.y = fmaf(c, a5, y.y);
        y.z = fmaf(c, a6, y.z); y.w = fmaf(c, a7, y.w);
        float4* hp = (float4*)&g_hfin[wi * 64 + q * 8];
        hp[0] = x; hp[1] = y;
    }
}

// ---------------- final: combined only (scores on side stream) ----------------
#define FIN_BLKS (NB / 16)    // 512
__global__ void k_final(const float* __restrict__ feat,
                        const float* __restrict__ weight,
                        const int* __restrict__ nodes,
                        float* __restrict__ outc) {
    int tx = threadIdx.x;
    int ty = threadIdx.y;
    int tid = ty * 16 + tx;

    __shared__ float sf[16][FEAT];
    __shared__ float shh[16][EMB];
    __shared__ int snd[16];
    int ibase = blockIdx.x * 16;

    if (tid < 16) snd[tid] = nodes[ibase + tid];
    __syncthreads();

    const float4* f4 = (const float4*)feat;
    const float4* h4 = (const float4*)g_hfin;   // coalesced per-entry rows
    for (int e = tid; e < 16 * 32; e += 256) {
        int n = e >> 5, k4 = e & 31;
        ((float4*)sf[n])[k4] = f4[snd[n] * 32 + k4];
    }
    for (int e = tid; e < 16 * 16; e += 256) {
        int n = e >> 4, k4 = e & 15;
        ((float4*)shh[n])[k4] = h4[ibase * 16 + e];
    }
    __syncthreads();

    float4 b = ((const float4*)g_bcomb)[tx];
    u64 A01 = pack2(b.x, b.y), A23 = pack2(b.z, b.w);
    const ulonglong2* Wv = (const ulonglong2*)weight;
#pragma unroll 8
    for (int k = 0; k < FEAT; k++) {
        u64 s = packss(sf[ty][k]);
        ulonglong2 w = Wv[k * 16 + tx];
        A01 = ffma2(s, w.x, A01);
        A23 = ffma2(s, w.y, A23);
    }
    const ulonglong2* Wc = (const ulonglong2*)g_Wcomb;
#pragma unroll 8
    for (int k = 0; k < EMB; k++) {
        u64 s = packss(shh[ty][k]);
        ulonglong2 w = Wc[k * 16 + tx];
        A01 = ffma2(s, w.x, A01);
        A23 = ffma2(s, w.y, A23);
    }
    float2 p0 = unpk(A01), p1 = unpk(A23);
    float4 o;
    o.x = fmaxf(p0.x, 0.0f); o.y = fmaxf(p0.y, 0.0f);
    o.z = fmaxf(p1.x, 0.0f); o.w = fmaxf(p1.y, 0.0f);
    ((float4*)outc)[(ibase + ty) * 16 + tx] = o;
}

extern "C" void kernel_launch(void* const* d_in, const int* in_sizes, int n_in,
                              void* d_out, int out_size) {
    const float* feat = (const float*)d_in[0];
    const float* Wclf = (const float*)d_in[1];
    const float* bclf = (const float*)d_in[2];
    const float* W1 = (const float*)d_in[3];
    const float* b1 = (const float*)d_in[4];
    const float* W2 = (const float*)d_in[5];
    const float* b2 = (const float*)d_in[6];
    const float* W3 = (const float*)d_in[7];
    const float* b3 = (const float*)d_in[8];
    const float* weight = (const float*)d_in[9];
    const int* nodes = (const int*)d_in[10];
    // d_in[11] = r1_neighs: dead branch (AGG_WEIGHT[0] == 0.0)
    const int* esrc = (const int*)d_in[12];
    const int* edst = (const int*)d_in[13];

    float* outc = (float*)d_out;          // [8192, 64]
    float* outs = outc + NB * EMB;        // [8192, 2]

    // Side stream: (dinv-free) MLP + wcomb + scores, overlapped with scatter/chain.
    cudaStream_t s2;
    cudaStreamCreateWithFlags(&s2, cudaStreamNonBlocking);
    cudaEvent_t evFork, evJoin, evJoin2;
    cudaEventCreateWithFlags(&evFork, cudaEventDisableTiming);
    cudaEventCreateWithFlags(&evJoin, cudaEventDisableTiming);
    cudaEventCreateWithFlags(&evJoin2, cudaEventDisableTiming);

    cudaEventRecord(evFork, 0);
    cudaStreamWaitEvent(s2, evFork, 0);
    k_mlp<<<(N_NODES + 63) / 64, 256, 0, s2>>>(feat, W1, b1, W2, b2);
    cudaEventRecord(evJoin, s2);          // mlp done (k_scale dependency)
    k_wcomb<<<17, 256, 0, s2>>>(W3, b3, weight);
    k_scores<<<NB * 32 / 256, 256, 0, s2>>>(feat, Wclf, bclf, nodes, outs);
    cudaEventRecord(evJoin2, s2);         // wcomb+scores done (k_final dependency)

    // Main (capture) stream: g_cursor is zero here (zero-init; reset in k_dinv).
    k_scatter<<<(NEDGE + 255) / 256, 256>>>(esrc, edst);
    k_dinv<<<(N_NODES + 255) / 256, 256>>>();

    cudaStreamWaitEvent(0, evJoin, 0);    // join mlp branch
    k_scale<<<(N_NODES * 8 + 255) / 256, 256>>>();   // f16a *= dinv

    // Factored chain: h_final = 0.84375 h - 2.53125 A^2 h + 2.53125 A^4 h - 0.84375 A^6 h
    // Stages 1-5 over all nodes; stage 6 only at the 8192 output list entries.
    const int SB = N_NODES / 8;
    k_spmv<false, true ><<<SB, 256>>>(0, 0.0f);        // a1 = A h     (a -> b)
    k_spmv<true,  true ><<<SB, 256>>>(1, -2.53125f);   // a2, acc -= 2.53125 a2
    k_spmv<false, true ><<<SB, 256>>>(0, 0.0f);        // a3
    k_spmv<true,  true ><<<SB, 256>>>(1, 2.53125f);    // a4, acc += 2.53125 a4
    k_spmv<false, true ><<<SB, 256>>>(0, 0.0f);        // a5           (a -> b)
    k_spmv6<<<NB / 8, 256>>>(nodes, -0.84375f);        // hfin[i] = acc - 0.84375 (A a5)

    cudaStreamWaitEvent(0, evJoin2, 0);   // ensure wcomb+scores precede k_final
    dim3 b16x16(16, 16);
    k_final<<<FIN_BLKS, b16x16>>>(feat, weight, nodes, outc);

    cudaEventDestroy(evFork);
    cudaEventDestroy(evJoin);
    cudaEventDestroy(evJoin2);
    cudaStreamDestroy(s2);
    (void)in_sizes; (void)n_in; (void)out_size;
}

// round 16
// speedup vs baseline: 1.0088x; 1.0026x over previous
#include <cuda_runtime.h>
#include <cuda_fp16.h>

#define N_NODES 50000
#define FEAT 128
#define EMB 64
#define NEDGE 1600000
#define NB 8192
#define CAP 128   // max in-degree bucket (Poisson(32): P(>128) ~ 0)
#define ZOFF (N_NODES << 7)   // byte offset of permanent zero row

// ---- scratch (device globals; zero-initialized at load) ----
__device__ __align__(16) float   g_acc[N_NODES * EMB];        // running even-power combo
__device__ __align__(16) __half2 g_f16a[(N_NODES + 1) * 32];  // gather copy (+zero row)
__device__ __align__(16) __half2 g_f16b[(N_NODES + 1) * 32];
__device__ float g_dinv[N_NODES];
__device__ int   g_cursor[N_NODES];          // per-dst fill cursor (reset in k_dinvscale)
__device__ int   g_cnt[N_NODES];             // frozen counts for spmv
__device__ int   g_colidx[N_NODES * CAP];    // padded buckets; entries are src*128 (byte offsets)
__device__ __align__(16) float g_Wcomb[EMB * EMB];   // W3 @ weight
__device__ float g_bcomb[EMB];                       // b3 @ weight

#define H2(x) (*(__half2*)&(x))

// ---- packed f32x2 helpers ----
typedef unsigned long long u64;
__device__ __forceinline__ u64 ffma2(u64 a, u64 b, u64 c) {
    u64 d;
    asm("fma.rn.f32x2 %0, %1, %2, %3;" : "=l"(d) : "l"(a), "l"(b), "l"(c));
    return d;
}
__device__ __forceinline__ u64 pack2(float x, float y) {
    u64 d; asm("mov.b64 %0, {%1, %2};" : "=l"(d) : "f"(x), "f"(y)); return d;
}
__device__ __forceinline__ u64 packss(float s) {
    u64 d; asm("mov.b64 %0, {%1, %1};" : "=l"(d) : "f"(s)); return d;
}
__device__ __forceinline__ float2 unpk(u64 v) {
    float2 r; asm("mov.b64 {%0, %1}, %2;" : "=f"(r.x), "=f"(r.y) : "l"(v)); return r;
}

// ---------------- scatter: 1 edge/thread for max atomic-latency hiding ----------------
__global__ void k_scatter(const int* __restrict__ src, const int* __restrict__ dst) {
    int e = blockIdx.x * blockDim.x + threadIdx.x;
    if (e < NEDGE) {
        int d = dst[e];
        int s = src[e];
        int p = atomicAdd(&g_cursor[d], 1);
        if (p < CAP) g_colidx[d * CAP + p] = s << 7;
    }
}

// ---------------- wcomb: Wcomb = W3 @ weight, bcomb = b3 @ weight (side stream) ----------------
__global__ void k_wcomb(const float* __restrict__ W3, const float* __restrict__ b3,
                        const float* __restrict__ weight) {
    int idx = blockIdx.x * blockDim.x + threadIdx.x;
    if (idx < EMB * EMB) {
        int k = idx / EMB, j = idx % EMB;
        float acc = 0.0f;
#pragma unroll 16
        for (int m = 0; m < FEAT; m++)
            acc = fmaf(W3[k * FEAT + m], weight[m * EMB + j], acc);
        g_Wcomb[idx] = acc;
    } else if (idx < EMB * EMB + EMB) {
        int j = idx - EMB * EMB;
        float acc = 0.0f;
#pragma unroll 16
        for (int m = 0; m < FEAT; m++)
            acc = fmaf(b3[m], weight[m * EMB + j], acc);
        g_bcomb[j] = acc;
    }
}

// ---------------- MLP: h = relu(relu(feat@W1+b1)@W2+b2) ----------------
// dinv-FREE (runs concurrently with scatter):
// writes acc = 0.84375*h (fp32) and f16a = half(h) UNSCALED.
__global__ __launch_bounds__(256) void k_mlp(const float* __restrict__ feat,
                      const float* __restrict__ W1, const float* __restrict__ b1,
                      const float* __restrict__ W2, const float* __restrict__ b2) {
    __shared__ float sfT[FEAT][64];   // [k][node]
    __shared__ float sh1T[EMB][68];   // [k][node], padded stride
    int tid = threadIdx.x;
    int tx = tid & 15;
    int ty = tid >> 4;
    int nbase = blockIdx.x * 64;

    {   // load features transposed
        int n = tid & 63;
        int gn = nbase + n;
        bool ok = gn < N_NODES;
        for (int p = tid >> 6; p < 32; p += 4) {
            float4 v = ok ? ((const float4*)feat)[gn * 32 + p]
                          : make_float4(0.f, 0.f, 0.f, 0.f);
            sfT[4 * p + 0][n] = v.x; sfT[4 * p + 1][n] = v.y;
            sfT[4 * p + 2][n] = v.z; sfT[4 * p + 3][n] = v.w;
        }
    }
    __syncthreads();

    u64 A[4][2];
    {
        float4 bb = ((const float4*)b1)[tx];
        u64 i01 = pack2(bb.x, bb.y), i23 = pack2(bb.z, bb.w);
        for (int j = 0; j < 4; j++) { A[j][0] = i01; A[j][1] = i23; }
    }
    const ulonglong2* W1v = (const ulonglong2*)W1;
#pragma unroll 4
    for (int k = 0; k < FEAT; k++) {
        ulonglong2 w = W1v[k * 16 + tx];
        float4 sv = *(const float4*)&sfT[k][4 * ty];
        u64 s;
        s = packss(sv.x); A[0][0] = ffma2(s, w.x, A[0][0]); A[0][1] = ffma2(s, w.y, A[0][1]);
        s = packss(sv.y); A[1][0] = ffma2(s, w.x, A[1][0]); A[1][1] = ffma2(s, w.y, A[1][1]);
        s = packss(sv.z); A[2][0] = ffma2(s, w.x, A[2][0]); A[2][1] = ffma2(s, w.y, A[2][1]);
        s = packss(sv.w); A[3][0] = ffma2(s, w.x, A[3][0]); A[3][1] = ffma2(s, w.y, A[3][1]);
    }
    for (int j = 0; j < 4; j++) {
        float2 p0 = unpk(A[j][0]), p1 = unpk(A[j][1]);
        int n = 4 * ty + j;
        sh1T[4 * tx + 0][n] = fmaxf(p0.x, 0.f);
        sh1T[4 * tx + 1][n] = fmaxf(p0.y, 0.f);
        sh1T[4 * tx + 2][n] = fmaxf(p1.x, 0.f);
        sh1T[4 * tx + 3][n] = fmaxf(p1.y, 0.f);
    }
    __syncthreads();

    {
        float4 bb = ((const float4*)b2)[tx];
        u64 i01 = pack2(bb.x, bb.y), i23 = pack2(bb.z, bb.w);
        for (int j = 0; j < 4; j++) { A[j][0] = i01; A[j][1] = i23; }
    }
    const ulonglong2* W2v = (const ulonglong2*)W2;
#pragma unroll 4
    for (int k = 0; k < EMB; k++) {
        ulonglong2 w = W2v[k * 16 + tx];
        float4 sv = *(const float4*)&sh1T[k][4 * ty];
        u64 s;
        s = packss(sv.x); A[0][0] = ffma2(s, w.x, A[0][0]); A[0][1] = ffma2(s, w.y, A[0][1]);
        s = packss(sv.y); A[1][0] = ffma2(s, w.x, A[1][0]); A[1][1] = ffma2(s, w.y, A[1][1]);
        s = packss(sv.z); A[2][0] = ffma2(s, w.x, A[2][0]); A[2][1] = ffma2(s, w.y, A[2][1]);
        s = packss(sv.w); A[3][0] = ffma2(s, w.x, A[3][0]); A[3][1] = ffma2(s, w.y, A[3][1]);
    }
    for (int j = 0; j < 4; j++) {
        int node = nbase + 4 * ty + j;
        if (node < N_NODES) {
            float2 p0 = unpk(A[j][0]), p1 = unpk(A[j][1]);
            float h0 = fmaxf(p0.x, 0.f), h1 = fmaxf(p0.y, 0.f);
            float h2 = fmaxf(p1.x, 0.f), h3 = fmaxf(p1.y, 0.f);
            ((float4*)g_acc)[node * 16 + tx] =
                make_float4(0.84375f * h0, 0.84375f * h1, 0.84375f * h2, 0.84375f * h3);
            g_f16a[node * 32 + 2 * tx + 0] = __floats2half2_rn(h0, h1);
            g_f16a[node * 32 + 2 * tx + 1] = __floats2half2_rn(h2, h3);
        }
    }
}

// ---------------- scores: center_scores = feat[nodes] @ Wclf + bclf (side stream) ----------------
__global__ void k_scores(const float* __restrict__ feat,
                         const float* __restrict__ Wclf,
                         const float* __restrict__ bclf,
                         const int* __restrict__ nodes,
                         float* __restrict__ outs) {
    int gt = blockIdx.x * blockDim.x + threadIdx.x;
    int w = gt >> 5, lane = gt & 31;
    if (w >= NB) return;
    int nd = nodes[w];
    float a0 = 0.0f, a1 = 0.0f;
    for (int k = lane; k < FEAT; k += 32) {
        float v = feat[nd * FEAT + k];
        a0 = fmaf(v, Wclf[2 * k], a0);
        a1 = fmaf(v, Wclf[2 * k + 1], a1);
    }
#pragma unroll
    for (int o = 16; o; o >>= 1) {
        a0 += __shfl_down_sync(0xffffffffu, a0, o);
        a1 += __shfl_down_sync(0xffffffffu, a1, o);
    }
    if (lane == 0) {
        outs[2 * w] = a0 + bclf[0];
        outs[2 * w + 1] = a1 + bclf[1];
    }
}

// ---------------- dinvscale: cnt/dinv/cursor-reset + f16a *= dinv (fused) ----------------
// Requires scatter (cursor) AND mlp (f16a). Thread per uint4; 8 lanes share a node.
__global__ void k_dinvscale() {
    int i = blockIdx.x * blockDim.x + threadIdx.x;   // over N_NODES*8 uint4
    if (i < N_NODES * 8) {
        int node = i >> 3;
        int c = g_cursor[node];
        float din = rsqrtf(fmaxf((float)c, 1.0f));
        if ((i & 7) == 0) {
            g_cnt[node] = min(c, CAP);
            g_dinv[node] = din;
            g_cursor[node] = 0;    // ready for next replay
        }
        uint4 v = ((uint4*)g_f16a)[i];
        float2 f0 = __half22float2(H2(v.x));
        float2 f1 = __half22float2(H2(v.y));
        float2 f2 = __half22float2(H2(v.z));
        float2 f3 = __half22float2(H2(v.w));
        __half2 h0 = __floats2half2_rn(f0.x * din, f0.y * din);
        __half2 h1 = __floats2half2_rn(f1.x * din, f1.y * din);
        __half2 h2 = __floats2half2_rn(f2.x * din, f2.y * din);
        __half2 h3 = __floats2half2_rn(f3.x * din, f3.y * din);
        uint4 o;
        o.x = *(unsigned*)&h0; o.y = *(unsigned*)&h1;
        o.z = *(unsigned*)&h2; o.w = *(unsigned*)&h3;
        ((uint4*)g_f16a)[i] = o;
    }
}

// ---------------- SpMV core (FROZEN R9 body): one warp per node ----------------
__device__ __forceinline__ void spmv_gather(const char* lptr, const int* col, int cnt,
                                            int g, float& a0, float& a1, float& a2,
                                            float& a3, float& a4, float& a5,
                                            float& a6, float& a7) {
    int i = 0;
    for (; i + 32 <= cnt; i += 32) {
#pragma unroll
        for (int j = 0; j < 8; j += 2) {
            int oA = col[i + 4 * j + g];
            int oB = col[i + 4 * j + 4 + g];
            uint4 va = *(const uint4*)(lptr + oA);
            uint4 vb = *(const uint4*)(lptr + oB);
            __half2 h0 = __hadd2(H2(va.x), H2(vb.x));
            __half2 h1 = __hadd2(H2(va.y), H2(vb.y));
            __half2 h2 = __hadd2(H2(va.z), H2(vb.z));
            __half2 h3 = __hadd2(H2(va.w), H2(vb.w));
            float2 f;
            f = __half22float2(h0); a0 += f.x; a1 += f.y;
            f = __half22float2(h1); a2 += f.x; a3 += f.y;
            f = __half22float2(h2); a4 += f.x; a5 += f.y;
            f = __half22float2(h3); a6 += f.x; a7 += f.y;
        }
    }
    if (i < cnt) {   // predicated full chunk for the tail
#pragma unroll
        for (int j = 0; j < 8; j += 2) {
            int eA = i + 4 * j + g;
            int eB = i + 4 * j + 4 + g;
            int oA = (eA < cnt) ? col[eA] : ZOFF;
            int oB = (eB < cnt) ? col[eB] : ZOFF;
            uint4 va = *(const uint4*)(lptr + oA);
            uint4 vb = *(const uint4*)(lptr + oB);
            __half2 h0 = __hadd2(H2(va.x), H2(vb.x));
            __half2 h1 = __hadd2(H2(va.y), H2(vb.y));
            __half2 h2 = __hadd2(H2(va.z), H2(vb.z));
            __half2 h3 = __hadd2(H2(va.w), H2(vb.w));
            float2 f;
            f = __half22float2(h0); a0 += f.x; a1 += f.y;
            f = __half22float2(h1); a2 += f.x; a3 += f.y;
            f = __half22float2(h2); a4 += f.x; a5 += f.y;
            f = __half22float2(h3); a6 += f.x; a7 += f.y;
        }
    }
}

#define SPMV_REDUCE() do { \
    a0 += __shfl_xor_sync(0xffffffffu, a0, 8);  a0 += __shfl_xor_sync(0xffffffffu, a0, 16); \
    a1 += __shfl_xor_sync(0xffffffffu, a1, 8);  a1 += __shfl_xor_sync(0xffffffffu, a1, 16); \
    a2 += __shfl_xor_sync(0xffffffffu, a2, 8);  a2 += __shfl_xor_sync(0xffffffffu, a2, 16); \
    a3 += __shfl_xor_sync(0xffffffffu, a3, 8);  a3 += __shfl_xor_sync(0xffffffffu, a3, 16); \
    a4 += __shfl_xor_sync(0xffffffffu, a4, 8);  a4 += __shfl_xor_sync(0xffffffffu, a4, 16); \
    a5 += __shfl_xor_sync(0xffffffffu, a5, 8);  a5 += __shfl_xor_sync(0xffffffffu, a5, 16); \
    a6 += __shfl_xor_sync(0xffffffffu, a6, 8);  a6 += __shfl_xor_sync(0xffffffffu, a6, 16); \
    a7 += __shfl_xor_sync(0xffffffffu, a7, 8);  a7 += __shfl_xor_sync(0xffffffffu, a7, 16); \
} while (0)

template <bool DO_ACC, bool DO_OUT>
__global__ __launch_bounds__(256, 8) void k_spmv(int parity, float coefAcc) {
    const char* __restrict__ inb = (const char*)(parity ? g_f16b : g_f16a);
    uint4* __restrict__ out = (uint4*)(parity ? g_f16a : g_f16b);
    int lane = threadIdx.x & 31;
    int d = blockIdx.x * 8 + (threadIdx.x >> 5);  // grid = 6250 exact
    int cnt = g_cnt[d];
    const int* __restrict__ col = g_colidx + d * CAP;
    int g = lane >> 3;
    int q = lane & 7;
    const char* lptr = inb + q * 16;

    float a0 = 0.f, a1 = 0.f, a2 = 0.f, a3 = 0.f;
    float a4 = 0.f, a5 = 0.f, a6 = 0.f, a7 = 0.f;
    spmv_gather(lptr, col, cnt, g, a0, a1, a2, a3, a4, a5, a6, a7);
    SPMV_REDUCE();

    float din = g_dinv[d];
    if (DO_OUT && lane < 8) {
        float s2 = din * din;   // out = (a*din)*din for next pre-scaled gather
        __half2 h0 = __floats2half2_rn(a0 * s2, a1 * s2);
        __half2 h1 = __floats2half2_rn(a2 * s2, a3 * s2);
        __half2 h2 = __floats2half2_rn(a4 * s2, a5 * s2);
        __half2 h3 = __floats2half2_rn(a6 * s2, a7 * s2);
        uint4 o;
        o.x = *(unsigned*)&h0; o.y = *(unsigned*)&h1;
        o.z = *(unsigned*)&h2; o.w = *(unsigned*)&h3;
        out[d * 8 + q] = o;
    }
    if (DO_ACC && lane >= 8 && lane < 16) {
        float c = coefAcc * din;    // acc += coef * (a*din)
        float4* ap = (float4*)&g_acc[d * 64 + q * 8];
        float4 x = ap[0], y = ap[1];
        x.x = fmaf(c, a0, x.x); x.y = fmaf(c, a1, x.y);
        x.z = fmaf(c, a2, x.z); x.w = fmaf(c, a3, x.w);
        y.x = fmaf(c, a4, y.x); y.y = fmaf(c, a5, y.y);
        y.z = fmaf(c, a6, y.z); y.w = fmaf(c, a7, y.w);
        ap[0] = x; ap[1] = y;
    }
}

// ---------------- final: fused stage-6 + combined GEMM ----------------
// 512 blocks x 256 threads; block handles 16 list entries.
// Phase 1: all threads gather feat rows into sf (overlaps phase 2 latency).
// Phase 2: warp w runs the stage-6 gather (A a5 at d=nodes[entry]) for
//          entries 2w, 2w+1 and writes the finished spectral row
//          acc[d] + coef*din*(A a5) straight into shh (no g_hfin).
// Phase 3: GEMM relu(sf@weight + shh@Wcomb + bcomb).
#define FIN_BLKS (NB / 16)    // 512
__global__ void k_final(const float* __restrict__ feat,
                        const float* __restrict__ weight,
                        const int* __restrict__ nodes,
                        float coefAcc,
                        float* __restrict__ outc) {
    int tx = threadIdx.x & 15;
    int ty = threadIdx.x >> 4;
    int tid = threadIdx.x;
    int lane = tid & 31;
    int w = tid >> 5;

    __shared__ float sf[16][FEAT];
    __shared__ float shh[16][EMB];
    __shared__ int snd[16];
    int ibase = blockIdx.x * 16;

    if (tid < 16) snd[tid] = nodes[ibase + tid];
    __syncthreads();

    // Phase 1: feature tile loads (issued first; latency overlaps phase 2)
    const float4* f4 = (const float4*)feat;
    for (int e = tid; e < 16 * 32; e += 256) {
        int n = e >> 5, k4 = e & 31;
        ((float4*)sf[n])[k4] = f4[snd[n] * 32 + k4];
    }

    // Phase 2: stage-6 gather for this warp's two entries
    {
        const char* inb = (const char*)g_f16b;   // a5 lives in buffer b
        int g = lane >> 3;
        int q = lane & 7;
        const char* lptr = inb + q * 16;
#pragma unroll
        for (int t = 0; t < 2; t++) {
            int entry = 2 * w + t;
            int d = snd[entry];
            int cnt = g_cnt[d];
            const int* col = g_colidx + d * CAP;
            float a0 = 0.f, a1 = 0.f, a2 = 0.f, a3 = 0.f;
            float a4 = 0.f, a5 = 0.f, a6 = 0.f, a7 = 0.f;
            spmv_gather(lptr, col, cnt, g, a0, a1, a2, a3, a4, a5, a6, a7);
            SPMV_REDUCE();
            if (lane < 8) {
                float c = coefAcc * g_dinv[d];
                const float4* ap = (const float4*)&g_acc[d * 64 + q * 8];
                float4 x = ap[0], y = ap[1];
                x.x = fmaf(c, a0, x.x); x.y = fmaf(c, a1, x.y);
                x.z = fmaf(c, a2, x.z); x.w = fmaf(c, a3, x.w);
                y.x = fmaf(c, a4, y.x); y.y = fmaf(c, a5, y.y);
                y.z = fmaf(c, a6, y.z); y.w = fmaf(c, a7, y.w);
                float4* hp = (float4*)&shh[entry][q * 8];
                hp[0] = x; hp[1] = y;
            }
        }
    }
    __syncthreads();

    // Phase 3: GEMM
    float4 b = ((const float4*)g_bcomb)[tx];
    u64 A01 = pack2(b.x, b.y), A23 = pack2(b.z, b.w);
    const ulonglong2* Wv = (const ulonglong2*)weight;
#pragma unroll 8
    for (int k = 0; k < FEAT; k++) {
        u64 s = packss(sf[ty][k]);
        ulonglong2 wv = Wv[k * 16 + tx];
        A01 = ffma2(s, wv.x, A01);
        A23 = ffma2(s, wv.y, A23);
    }
    const ulonglong2* Wc = (const ulonglong2*)g_Wcomb;
#pragma unroll 8
    for (int k = 0; k < EMB; k++) {
        u64 s = packss(shh[ty][k]);
        ulonglong2 wv = Wc[k * 16 + tx];
        A01 = ffma2(s, wv.x, A01);
        A23 = ffma2(s, wv.y, A23);
    }
    float2 p0 = unpk(A01), p1 = unpk(A23);
    float4 o;
    o.x = fmaxf(p0.x, 0.0f); o.y = fmaxf(p0.y, 0.0f);
    o.z = fmaxf(p1.x, 0.0f); o.w = fmaxf(p1.y, 0.0f);
    ((float4*)outc)[(ibase + ty) * 16 + tx] = o;
}

extern "C" void kernel_launch(void* const* d_in, const int* in_sizes, int n_in,
                              void* d_out, int out_size) {
    const float* feat = (const float*)d_in[0];
    const float* Wclf = (const float*)d_in[1];
    const float* bclf = (const float*)d_in[2];
    const float* W1 = (const float*)d_in[3];
    const float* b1 = (const float*)d_in[4];
    const float* W2 = (const float*)d_in[5];
    const float* b2 = (const float*)d_in[6];
    const float* W3 = (const float*)d_in[7];
    const float* b3 = (const float*)d_in[8];
    const float* weight = (const float*)d_in[9];
    const int* nodes = (const int*)d_in[10];
    // d_in[11] = r1_neighs: dead branch (AGG_WEIGHT[0] == 0.0)
    const int* esrc = (const int*)d_in[12];
    const int* edst = (const int*)d_in[13];

    float* outc = (float*)d_out;          // [8192, 64]
    float* outs = outc + NB * EMB;        // [8192, 2]

    // Side stream: (dinv-free) MLP + wcomb + scores, overlapped with scatter/chain.
    cudaStream_t s2;
    cudaStreamCreateWithFlags(&s2, cudaStreamNonBlocking);
    cudaEvent_t evFork, evJoin, evJoin2;
    cudaEventCreateWithFlags(&evFork, cudaEventDisableTiming);
    cudaEventCreateWithFlags(&evJoin, cudaEventDisableTiming);
    cudaEventCreateWithFlags(&evJoin2, cudaEventDisableTiming);

    cudaEventRecord(evFork, 0);
    cudaStreamWaitEvent(s2, evFork, 0);
    k_mlp<<<(N_NODES + 63) / 64, 256, 0, s2>>>(feat, W1, b1, W2, b2);
    cudaEventRecord(evJoin, s2);          // mlp done (k_dinvscale dependency)
    k_wcomb<<<17, 256, 0, s2>>>(W3, b3, weight);
    k_scores<<<NB * 32 / 256, 256, 0, s2>>>(feat, Wclf, bclf, nodes, outs);
    cudaEventRecord(evJoin2, s2);         // wcomb+scores done (k_final dependency)

    // Main (capture) stream: g_cursor is zero here (zero-init; reset in k_dinvscale).
    k_scatter<<<(NEDGE + 255) / 256, 256>>>(esrc, edst);

    cudaStreamWaitEvent(0, evJoin, 0);    // join mlp branch
    k_dinvscale<<<(N_NODES * 8 + 255) / 256, 256>>>();   // dinv + f16a *= dinv

    // Factored chain: h_final = 0.84375 h - 2.53125 A^2 h + 2.53125 A^4 h - 0.84375 A^6 h
    // Stages 1-5 over all nodes; stage 6 fused into k_final at list entries.
    const int SB = N_NODES / 8;
    k_spmv<false, true ><<<SB, 256>>>(0, 0.0f);        // a1 = A h     (a -> b)
    k_spmv<true,  true ><<<SB, 256>>>(1, -2.53125f);   // a2, acc -= 2.53125 a2
    k_spmv<false, true ><<<SB, 256>>>(0, 0.0f);        // a3
    k_spmv<true,  true ><<<SB, 256>>>(1, 2.53125f);    // a4, acc += 2.53125 a4
    k_spmv<false, true ><<<SB, 256>>>(0, 0.0f);        // a5           (a -> b)

    cudaStreamWaitEvent(0, evJoin2, 0);   // ensure wcomb+scores precede k_final
    k_final<<<FIN_BLKS, 256>>>(feat, weight, nodes, -0.84375f, outc);

    cudaEventDestroy(evFork);
    cudaEventDestroy(evJoin);
    cudaEventDestroy(evJoin2);
    cudaStreamDestroy(s2);
    (void)in_sizes; (void)n_in; (void)out_size;
}